// round 5
// baseline (speedup 1.0000x reference)
#include <cuda_runtime.h>

// Problem constants
#define NN      8192        // N edges
#define EE      256         // embedding dim
#define SS      16          // survival steps
#define NSRC    10000
#define MINDST  10000
#define SURV_ROWS (SS * NN)             // 131072
#define EDGE_BLOCKS (NN / 8)            // 1024  (8 warps/block, warp-per-edge)
#define SURV_BLOCKS (SURV_ROWS / 8)     // 16384 (8 warps/block, warp-per-row)

// Scratch (no allocation allowed -> __device__ globals)
__device__ float  g_td_uv[NN];
__device__ double g_part_lambda[EDGE_BLOCKS];
__device__ double g_part_acc[EDGE_BLOCKS];
__device__ double g_part_surv[SURV_BLOCKS];

__device__ __forceinline__ float hawkes(float dot, float td,
                                        float b, float psi, float alpha, float w_t)
{
    float g  = dot + b + alpha * expf(-w_t * td * (1.0f / 5000.0f));
    float gp = fminf(fmaxf(g / (psi + 1e-7f), -75.0f), 75.0f);
    return psi * (log1pf(expf(-gp)) + gp);
}

// ---------------------------------------------------------------------------
// Kernel 1: per-edge path. warp-per-edge, 8 edges/block.
//   - td_uv[i] -> scratch
//   - -log(lambda_uv + 1e-7) partials
//   - use_accu * event_inten_accu[src, dst-MIN_DST] partials
// ---------------------------------------------------------------------------
__global__ __launch_bounds__(256)
void edge_kernel(const float* __restrict__ emb,
                 const int*   __restrict__ assoc,
                 const int*   __restrict__ src,
                 const int*   __restrict__ dst,
                 const float* __restrict__ last_update,
                 const float* __restrict__ cur_time,
                 const float* __restrict__ last_time_pos,
                 const float* __restrict__ accu,
                 const float* __restrict__ W,
                 const float* __restrict__ b,
                 const float* __restrict__ psi,
                 const float* __restrict__ alpha,
                 const float* __restrict__ w_t)
{
    __shared__ __align__(16) float sW[2 * EE];
    __shared__ double s_l[8];
    __shared__ double s_a[8];

    int tid = threadIdx.x;
    for (int j = tid; j < 2 * EE; j += 256) sW[j] = W[j];
    __syncthreads();

    int warp = tid >> 5, lane = tid & 31;
    int e = blockIdx.x * 8 + warp;          // always < NN

    int   s   = src[e];
    int   d   = dst[e];
    int   as  = assoc[s];
    int   ad  = assoc[d];
    float lu  = fmaxf(last_update[as], last_update[ad]);
    float ltp = last_time_pos[e];
    float td  = cur_time[e] - fmaxf(lu, ltp);
    if (lane == 0) g_td_uv[e] = td;

    const float4* zs = (const float4*)(emb + (size_t)as * EE);
    const float4* zd = (const float4*)(emb + (size_t)ad * EE);
    const float4* w4 = (const float4*)sW;

    float acc = 0.0f;
#pragma unroll
    for (int k = 0; k < 2; k++) {
        float4 a  = zs[k * 32 + lane];
        float4 wa = w4[k * 32 + lane];
        acc += a.x * wa.x + a.y * wa.y + a.z * wa.z + a.w * wa.w;
        float4 v  = zd[k * 32 + lane];
        float4 wv = w4[64 + k * 32 + lane];
        acc += v.x * wv.x + v.y * wv.y + v.z * wv.z + v.w * wv.w;
    }
#pragma unroll
    for (int o = 16; o; o >>= 1) acc += __shfl_xor_sync(0xffffffffu, acc, o);

    if (lane == 0) {
        float lam = hawkes(acc, td, b[0], psi[0], alpha[0], w_t[0]);
        s_l[warp] = -(double)logf(lam + 1e-7f);
        float ua  = (ltp >= lu) ? 1.0f : 0.0f;
        s_a[warp] = (double)(ua * accu[(size_t)s * NSRC + (size_t)(d - MINDST)]);
    }
    __syncthreads();
    if (tid == 0) {
        double a = 0.0, c = 0.0;
#pragma unroll
        for (int k = 0; k < 8; k++) { a += s_l[k]; c += s_a[k]; }
        g_part_lambda[blockIdx.x] = a;
        g_part_acc[blockIdx.x]    = c;
    }
}

// ---------------------------------------------------------------------------
// Kernel 2: survival GEMV, fused with Hawkes + integral contribution.
// warp-per-row (row = s*N + i), streams u_non/v_non once. Accumulates
// lambda_surv(row) * td_uv[row % N] into block partials (double).
// ---------------------------------------------------------------------------
__global__ __launch_bounds__(256)
void surv_kernel(const float* __restrict__ u,
                 const float* __restrict__ v,
                 const float* __restrict__ tdstep,
                 const float* __restrict__ W,
                 const float* __restrict__ b,
                 const float* __restrict__ psi,
                 const float* __restrict__ alpha,
                 const float* __restrict__ w_t)
{
    __shared__ __align__(16) float sW[2 * EE];
    __shared__ double s_p[8];

    int tid = threadIdx.x;
    for (int j = tid; j < 2 * EE; j += 256) sW[j] = W[j];
    __syncthreads();

    int warp = tid >> 5, lane = tid & 31;
    size_t row = (size_t)blockIdx.x * 8 + warp;   // < SURV_ROWS

    const float4* ur = (const float4*)(u + row * EE);
    const float4* vr = (const float4*)(v + row * EE);
    const float4* w4 = (const float4*)sW;

    float acc = 0.0f;
#pragma unroll
    for (int k = 0; k < 2; k++) {
        float4 a  = ur[k * 32 + lane];
        float4 wa = w4[k * 32 + lane];
        acc += a.x * wa.x + a.y * wa.y + a.z * wa.z + a.w * wa.w;
        float4 c  = vr[k * 32 + lane];
        float4 wv = w4[64 + k * 32 + lane];
        acc += c.x * wv.x + c.y * wv.y + c.z * wv.z + c.w * wv.w;
    }
#pragma unroll
    for (int o = 16; o; o >>= 1) acc += __shfl_xor_sync(0xffffffffu, acc, o);

    if (lane == 0) {
        int   i   = (int)(row & (NN - 1));
        float tdu = g_td_uv[i];
        float td  = tdstep[row] * tdu;
        float lam = hawkes(acc, td, b[0], psi[0], alpha[0], w_t[0]);
        s_p[warp] = (double)lam * (double)tdu;
    }
    __syncthreads();
    if (tid == 0) {
        double t = 0.0;
#pragma unroll
        for (int k = 0; k < 8; k++) t += s_p[k];
        g_part_surv[blockIdx.x] = t;
    }
}

// ---------------------------------------------------------------------------
// Kernel 3: deterministic final reduction -> out[0], out[1]
// ---------------------------------------------------------------------------
__global__ __launch_bounds__(256)
void final_kernel(float* __restrict__ out)
{
    __shared__ double sh[256];
    int tid = threadIdx.x;

    // surv partials
    double s = 0.0;
    for (int j = tid; j < SURV_BLOCKS; j += 256) s += g_part_surv[j];
    sh[tid] = s; __syncthreads();
    for (int o = 128; o; o >>= 1) { if (tid < o) sh[tid] += sh[tid + o]; __syncthreads(); }
    double surv = sh[0]; __syncthreads();

    // lambda partials
    double l = 0.0;
    for (int j = tid; j < EDGE_BLOCKS; j += 256) l += g_part_lambda[j];
    sh[tid] = l; __syncthreads();
    for (int o = 128; o; o >>= 1) { if (tid < o) sh[tid] += sh[tid + o]; __syncthreads(); }
    double lam = sh[0]; __syncthreads();

    // accu partials
    double a = 0.0;
    for (int j = tid; j < EDGE_BLOCKS; j += 256) a += g_part_acc[j];
    sh[tid] = a; __syncthreads();
    for (int o = 128; o; o >>= 1) { if (tid < o) sh[tid] += sh[tid + o]; __syncthreads(); }

    if (tid == 0) {
        double loss_lambda = lam / (double)NN;
        double loss_surv   = (surv / (double)SS + sh[0]) / (double)NN;
        out[0] = (float)loss_lambda;
        out[1] = (float)loss_surv;
    }
}

// ---------------------------------------------------------------------------
// Inputs (metadata order):
//  0 all_embeddings (20000,256) f32   1 assoc (20000,) i32
//  2 src (8192,) i32                  3 pos_dst (8192,) i32
//  4 last_update (20000,) f32         5 cur_time (8192,) f32
//  6 u_non_embeddings (131072,256)    7 v_non_embeddings (131072,256)
//  8 last_time_pos (8192,) f32        9 td_surv_step (16,8192) f32
// 10 event_inten_accu (10000,10000)  11 W_omega (1,512)
// 12 b_omega (1,)  13 psi (1,)  14 alpha (1,)  15 w_t (1,)
// ---------------------------------------------------------------------------
extern "C" void kernel_launch(void* const* d_in, const int* in_sizes, int n_in,
                              void* d_out, int out_size)
{
    const float* emb     = (const float*)d_in[0];
    const int*   assoc   = (const int*)  d_in[1];
    const int*   src     = (const int*)  d_in[2];
    const int*   dst     = (const int*)  d_in[3];
    const float* lupd    = (const float*)d_in[4];
    const float* ctime   = (const float*)d_in[5];
    const float* u_non   = (const float*)d_in[6];
    const float* v_non   = (const float*)d_in[7];
    const float* ltp     = (const float*)d_in[8];
    const float* tdstep  = (const float*)d_in[9];
    const float* accu    = (const float*)d_in[10];
    const float* W       = (const float*)d_in[11];
    const float* b       = (const float*)d_in[12];
    const float* psi     = (const float*)d_in[13];
    const float* alpha   = (const float*)d_in[14];
    const float* w_t     = (const float*)d_in[15];
    float* out = (float*)d_out;

    edge_kernel<<<EDGE_BLOCKS, 256>>>(emb, assoc, src, dst, lupd, ctime, ltp,
                                      accu, W, b, psi, alpha, w_t);
    surv_kernel<<<SURV_BLOCKS, 256>>>(u_non, v_non, tdstep, W, b, psi, alpha, w_t);
    final_kernel<<<1, 256>>>(out);
}

// round 6
// speedup vs baseline: 1.2703x; 1.2703x over previous
#include <cuda_runtime.h>

// Problem constants
#define NN      8192        // N edges
#define EE      256         // embedding dim
#define SS      16          // survival steps
#define NSRC    10000
#define MINDST  10000
#define SURV_ROWS  (SS * NN)            // 131072
#define TOTAL_ROWS (SURV_ROWS + NN)     // 139264 (surv rows + edge rows)

#define PRE_BLOCKS  32                  // 32 x 256 = 8192 edges
#define MAIN_BLOCKS 1184                // 148 SMs x 8 blocks, persistent-ish
#define MAIN_WARPS  (MAIN_BLOCKS * 8)   // 9472 warps, ~14.7 rows each

// Scratch (no allocation allowed -> __device__ globals)
__device__ float  g_td_uv[NN];
__device__ int    g_as[NN];
__device__ int    g_ad[NN];
__device__ double g_part_acc[PRE_BLOCKS];
__device__ double g_part_surv[MAIN_BLOCKS];
__device__ double g_part_lam[MAIN_BLOCKS];

__device__ __forceinline__ float hawkes(float dot, float td,
                                        float b, float psi, float alpha, float w_t)
{
    float g  = dot + b + alpha * expf(-w_t * td * (1.0f / 5000.0f));
    float gp = fminf(fmaxf(g / (psi + 1e-7f), -75.0f), 75.0f);
    return psi * (log1pf(expf(-gp)) + gp);
}

// ---------------------------------------------------------------------------
// Kernel 1 (tiny): per-edge scalar path. Resolves all indirection chains so
// the main streaming kernel has none.
//   - td_uv[e] = cur_time - max(max(lu_src, lu_dst), last_time_pos)
//   - g_as/g_ad = assoc[src]/assoc[dst]
//   - accu-term block partials (double)
// ---------------------------------------------------------------------------
__global__ __launch_bounds__(256)
void pre_kernel(const int*   __restrict__ assoc,
                const int*   __restrict__ src,
                const int*   __restrict__ dst,
                const float* __restrict__ last_update,
                const float* __restrict__ cur_time,
                const float* __restrict__ last_time_pos,
                const float* __restrict__ accu)
{
    __shared__ double sh[256];
    int tid = threadIdx.x;
    int e   = blockIdx.x * 256 + tid;        // always < NN

    int   s   = src[e];
    int   d   = dst[e];
    int   as  = assoc[s];
    int   ad  = assoc[d];
    float lu  = fmaxf(last_update[as], last_update[ad]);
    float ltp = last_time_pos[e];
    float td  = cur_time[e] - fmaxf(lu, ltp);

    g_td_uv[e] = td;
    g_as[e]    = as;
    g_ad[e]    = ad;

    float ua = (ltp >= lu) ? 1.0f : 0.0f;
    sh[tid] = (double)(ua * accu[(size_t)s * NSRC + (size_t)(d - MINDST)]);
    __syncthreads();
    for (int o = 128; o; o >>= 1) {
        if (tid < o) sh[tid] += sh[tid + o];
        __syncthreads();
    }
    if (tid == 0) g_part_acc[blockIdx.x] = sh[0];
}

// ---------------------------------------------------------------------------
// Kernel 2: unified streaming kernel. Grid-stride warp-per-row over
// TOTAL_ROWS rows:
//   rows [0, SURV_ROWS)         : survival GEMV rows (u/v stream, 268 MB)
//   rows [SURV_ROWS, TOTAL_ROWS): edge rows (gathered embedding pairs, 16 MB)
// W lives entirely in 16 registers per lane (indexed by lane only).
// Per-warp double accumulators; one block-reduced partial pair per block.
// ---------------------------------------------------------------------------
__global__ __launch_bounds__(256)
void main_kernel(const float* __restrict__ u,
                 const float* __restrict__ v,
                 const float* __restrict__ tdstep,
                 const float* __restrict__ emb,
                 const float* __restrict__ W,
                 const float* __restrict__ b_,
                 const float* __restrict__ psi_,
                 const float* __restrict__ alpha_,
                 const float* __restrict__ wt_)
{
    int tid = threadIdx.x, warp = tid >> 5, lane = tid & 31;

    // W into registers: lane k owns float4s {k, 32+k, 64+k, 96+k} of W[512].
    const float4* w4 = (const float4*)W;
    const float4 wu0 = w4[lane];
    const float4 wu1 = w4[32 + lane];
    const float4 wv0 = w4[64 + lane];
    const float4 wv1 = w4[96 + lane];

    const float b     = b_[0];
    const float psi   = psi_[0];
    const float alpha = alpha_[0];
    const float wt    = wt_[0];

    double acc_s = 0.0;   // sum of lambda_surv * td_uv
    double acc_l = 0.0;   // sum of -log(lambda_uv + 1e-7)

    int gw = blockIdx.x * 8 + warp;
    for (int r = gw; r < TOTAL_ROWS; r += MAIN_WARPS) {
        const float4* pu;
        const float4* pv;
        float tdu = 0.0f, td;
        bool is_surv = (r < SURV_ROWS);

        if (is_surv) {
            pu  = (const float4*)(u + (size_t)r * EE);
            pv  = (const float4*)(v + (size_t)r * EE);
            tdu = g_td_uv[r & (NN - 1)];
            td  = tdstep[r] * tdu;
        } else {
            int e = r - SURV_ROWS;
            pu = (const float4*)(emb + (size_t)g_as[e] * EE);
            pv = (const float4*)(emb + (size_t)g_ad[e] * EE);
            td = g_td_uv[e];
        }

        float4 a0 = pu[lane];
        float4 a1 = pu[32 + lane];
        float4 c0 = pv[lane];
        float4 c1 = pv[32 + lane];

        float acc = a0.x * wu0.x + a0.y * wu0.y + a0.z * wu0.z + a0.w * wu0.w
                  + a1.x * wu1.x + a1.y * wu1.y + a1.z * wu1.z + a1.w * wu1.w
                  + c0.x * wv0.x + c0.y * wv0.y + c0.z * wv0.z + c0.w * wv0.w
                  + c1.x * wv1.x + c1.y * wv1.y + c1.z * wv1.z + c1.w * wv1.w;

#pragma unroll
        for (int o = 16; o; o >>= 1) acc += __shfl_xor_sync(0xffffffffu, acc, o);

        if (lane == 0) {
            float lam = hawkes(acc, td, b, psi, alpha, wt);
            if (is_surv) acc_s += (double)lam * (double)tdu;
            else         acc_l -= (double)logf(lam + 1e-7f);
        }
    }

    __shared__ double ssv[8];
    __shared__ double slm[8];
    if (lane == 0) { ssv[warp] = acc_s; slm[warp] = acc_l; }
    __syncthreads();
    if (tid == 0) {
        double a = 0.0, c = 0.0;
#pragma unroll
        for (int k = 0; k < 8; k++) { a += ssv[k]; c += slm[k]; }
        g_part_surv[blockIdx.x] = a;
        g_part_lam[blockIdx.x]  = c;
    }
}

// ---------------------------------------------------------------------------
// Kernel 3: deterministic final reduction -> out[0], out[1]
// ---------------------------------------------------------------------------
__global__ __launch_bounds__(256)
void final_kernel(float* __restrict__ out)
{
    __shared__ double sh[256];
    int tid = threadIdx.x;

    // surv partials
    double s = 0.0;
    for (int j = tid; j < MAIN_BLOCKS; j += 256) s += g_part_surv[j];
    sh[tid] = s; __syncthreads();
    for (int o = 128; o; o >>= 1) { if (tid < o) sh[tid] += sh[tid + o]; __syncthreads(); }
    double surv = sh[0]; __syncthreads();

    // lambda partials
    double l = 0.0;
    for (int j = tid; j < MAIN_BLOCKS; j += 256) l += g_part_lam[j];
    sh[tid] = l; __syncthreads();
    for (int o = 128; o; o >>= 1) { if (tid < o) sh[tid] += sh[tid + o]; __syncthreads(); }
    double lam = sh[0]; __syncthreads();

    // accu partials
    double a = 0.0;
    if (tid < PRE_BLOCKS) a = g_part_acc[tid];
    sh[tid] = a; __syncthreads();
    for (int o = 128; o; o >>= 1) { if (tid < o) sh[tid] += sh[tid + o]; __syncthreads(); }

    if (tid == 0) {
        double loss_lambda = lam / (double)NN;
        double loss_surv   = (surv / (double)SS + sh[0]) / (double)NN;
        out[0] = (float)loss_lambda;
        out[1] = (float)loss_surv;
    }
}

// ---------------------------------------------------------------------------
// Inputs (metadata order):
//  0 all_embeddings (20000,256) f32   1 assoc (20000,) i32
//  2 src (8192,) i32                  3 pos_dst (8192,) i32
//  4 last_update (20000,) f32         5 cur_time (8192,) f32
//  6 u_non_embeddings (131072,256)    7 v_non_embeddings (131072,256)
//  8 last_time_pos (8192,) f32        9 td_surv_step (16,8192) f32
// 10 event_inten_accu (10000,10000)  11 W_omega (1,512)
// 12 b_omega (1,)  13 psi (1,)  14 alpha (1,)  15 w_t (1,)
// ---------------------------------------------------------------------------
extern "C" void kernel_launch(void* const* d_in, const int* in_sizes, int n_in,
                              void* d_out, int out_size)
{
    const float* emb     = (const float*)d_in[0];
    const int*   assoc   = (const int*)  d_in[1];
    const int*   src     = (const int*)  d_in[2];
    const int*   dst     = (const int*)  d_in[3];
    const float* lupd    = (const float*)d_in[4];
    const float* ctime   = (const float*)d_in[5];
    const float* u_non   = (const float*)d_in[6];
    const float* v_non   = (const float*)d_in[7];
    const float* ltp     = (const float*)d_in[8];
    const float* tdstep  = (const float*)d_in[9];
    const float* accu    = (const float*)d_in[10];
    const float* W       = (const float*)d_in[11];
    const float* b       = (const float*)d_in[12];
    const float* psi     = (const float*)d_in[13];
    const float* alpha   = (const float*)d_in[14];
    const float* w_t     = (const float*)d_in[15];
    float* out = (float*)d_out;

    pre_kernel<<<PRE_BLOCKS, 256>>>(assoc, src, dst, lupd, ctime, ltp, accu);
    main_kernel<<<MAIN_BLOCKS, 256>>>(u_non, v_non, tdstep, emb, W,
                                      b, psi, alpha, w_t);
    final_kernel<<<1, 256>>>(out);
}

// round 10
// speedup vs baseline: 1.3938x; 1.0972x over previous
#include <cuda_runtime.h>

// Problem constants
#define NN      8192        // N edges
#define EE      256         // embedding dim
#define SS      16          // survival steps
#define NSRC    10000
#define MINDST  10000
#define SURV_ROWS  (SS * NN)            // 131072
#define TOTAL_ROWS (SURV_ROWS + NN)     // 139264 (surv rows + edge rows)

#define PRE_BLOCKS  64                  // 64 x 128 = 8192 edges
#define MAIN_BLOCKS 1184
#define MAIN_WARPS  (MAIN_BLOCKS * 8)   // 9472 warps; pairs of rows per iter

// Scratch (no allocation allowed -> __device__ globals)
__device__ float  g_td_uv[NN];
__device__ int    g_as[NN];
__device__ int    g_ad[NN];
__device__ float  g_ua[NN];
__device__ int    g_accu_idx[NN];
__device__ double g_part_surv[MAIN_BLOCKS];
__device__ double g_part_lam[MAIN_BLOCKS];
__device__ double g_part_acc[MAIN_BLOCKS];
__device__ unsigned int g_done = 0;

__device__ __forceinline__ float hawkes(float dot, float td,
                                        float b, float psi, float alpha, float w_t)
{
    float g  = dot + b + alpha * expf(-w_t * td * (1.0f / 5000.0f));
    float gp = fminf(fmaxf(g / (psi + 1e-7f), -75.0f), 75.0f);
    return psi * (log1pf(expf(-gp)) + gp);
}

// ---------------------------------------------------------------------------
// Kernel 1 (tiny): resolves indirection chains only. No accu load (that
// random-DRAM gather is folded into the streaming kernel where it hides).
// ---------------------------------------------------------------------------
__global__ __launch_bounds__(128)
void pre_kernel(const int*   __restrict__ assoc,
                const int*   __restrict__ src,
                const int*   __restrict__ dst,
                const float* __restrict__ last_update,
                const float* __restrict__ cur_time,
                const float* __restrict__ last_time_pos)
{
    int e = blockIdx.x * 128 + threadIdx.x;      // always < NN
    int   s   = src[e];
    int   d   = dst[e];
    int   as  = assoc[s];
    int   ad  = assoc[d];
    float lu  = fmaxf(last_update[as], last_update[ad]);
    float ltp = last_time_pos[e];

    g_td_uv[e]    = cur_time[e] - fmaxf(lu, ltp);
    g_as[e]       = as;
    g_ad[e]       = ad;
    g_ua[e]       = (ltp >= lu) ? 1.0f : 0.0f;
    g_accu_idx[e] = s * NSRC + (d - MINDST);
}

// ---------------------------------------------------------------------------
// Kernel 2: unified streaming kernel.
//  - grid-stride, warp processes row pair (r, r+1) per iteration (2x MLP)
//  - rows [0, SURV_ROWS): survival GEMV rows (u/v stream)
//  - rows [SURV_ROWS, TOTAL_ROWS): edge rows (gathered embedding pairs)
//  - threads with global id < NN also do one random accu gather (hidden)
//  - last-done block performs the deterministic final reduction -> out
// ---------------------------------------------------------------------------
__global__ __launch_bounds__(256)
void main_kernel(const float* __restrict__ u,
                 const float* __restrict__ v,
                 const float* __restrict__ tdstep,
                 const float* __restrict__ emb,
                 const float* __restrict__ accu,
                 const float* __restrict__ W,
                 const float* __restrict__ b_,
                 const float* __restrict__ psi_,
                 const float* __restrict__ alpha_,
                 const float* __restrict__ wt_,
                 float* __restrict__ out)
{
    int tid = threadIdx.x, warp = tid >> 5, lane = tid & 31;

    // W in registers: lane k owns float4s {k, 32+k, 64+k, 96+k} of W[512].
    const float4* w4 = (const float4*)W;
    const float4 wu0 = w4[lane];
    const float4 wu1 = w4[32 + lane];
    const float4 wv0 = w4[64 + lane];
    const float4 wv1 = w4[96 + lane];

    const float b     = b_[0];
    const float psi   = psi_[0];
    const float alpha = alpha_[0];
    const float wt    = wt_[0];

    double acc_s = 0.0;   // sum lambda_surv * td_uv
    double acc_l = 0.0;   // sum -log(lambda_uv + 1e-7)
    double acc_a = 0.0;   // sum use_accu * accu[...]

    // Hidden random gather: one accu element per early global thread.
    int gtid = blockIdx.x * 256 + tid;
    if (gtid < NN)
        acc_a = (double)(g_ua[gtid] * __ldg(&accu[g_accu_idx[gtid]]));

    const float4* u4 = (const float4*)u;
    const float4* v4 = (const float4*)v;
    const float4* e4 = (const float4*)emb;

    int gw = blockIdx.x * 8 + warp;
    for (int r = 2 * gw; r < TOTAL_ROWS; r += 2 * MAIN_WARPS) {
        // ---- row r0 = r ----
        const float4 *pu0, *pv0;
        float tdu0 = 0.0f, td0;
        bool surv0 = (r < SURV_ROWS);
        if (surv0) {
            pu0 = u4 + (size_t)r * 64;
            pv0 = v4 + (size_t)r * 64;
            tdu0 = g_td_uv[r & (NN - 1)];
            td0  = tdstep[r] * tdu0;
        } else {
            int e = r - SURV_ROWS;
            pu0 = e4 + (size_t)g_as[e] * 64;
            pv0 = e4 + (size_t)g_ad[e] * 64;
            td0 = g_td_uv[e];
        }
        // ---- row r1 = r+1 (TOTAL_ROWS even, r even -> always valid) ----
        int r1 = r + 1;
        const float4 *pu1, *pv1;
        float tdu1 = 0.0f, td1;
        bool surv1 = (r1 < SURV_ROWS);
        if (surv1) {
            pu1 = u4 + (size_t)r1 * 64;
            pv1 = v4 + (size_t)r1 * 64;
            tdu1 = g_td_uv[r1 & (NN - 1)];
            td1  = tdstep[r1] * tdu1;
        } else {
            int e = r1 - SURV_ROWS;
            pu1 = e4 + (size_t)g_as[e] * 64;
            pv1 = e4 + (size_t)g_ad[e] * 64;
            td1 = g_td_uv[e];
        }

        // 8 independent LDG.128 per lane (streaming, evict-first)
        float4 a0 = __ldcs(pu0 + lane);
        float4 a1 = __ldcs(pu0 + 32 + lane);
        float4 c0 = __ldcs(pv0 + lane);
        float4 c1 = __ldcs(pv0 + 32 + lane);
        float4 d0 = __ldcs(pu1 + lane);
        float4 d1 = __ldcs(pu1 + 32 + lane);
        float4 f0 = __ldcs(pv1 + lane);
        float4 f1 = __ldcs(pv1 + 32 + lane);

        float dot0 = a0.x * wu0.x + a0.y * wu0.y + a0.z * wu0.z + a0.w * wu0.w
                   + a1.x * wu1.x + a1.y * wu1.y + a1.z * wu1.z + a1.w * wu1.w
                   + c0.x * wv0.x + c0.y * wv0.y + c0.z * wv0.z + c0.w * wv0.w
                   + c1.x * wv1.x + c1.y * wv1.y + c1.z * wv1.z + c1.w * wv1.w;
        float dot1 = d0.x * wu0.x + d0.y * wu0.y + d0.z * wu0.z + d0.w * wu0.w
                   + d1.x * wu1.x + d1.y * wu1.y + d1.z * wu1.z + d1.w * wu1.w
                   + f0.x * wv0.x + f0.y * wv0.y + f0.z * wv0.z + f0.w * wv0.w
                   + f1.x * wv1.x + f1.y * wv1.y + f1.z * wv1.z + f1.w * wv1.w;

#pragma unroll
        for (int o = 16; o; o >>= 1) {          // two interleaved shfl chains
            dot0 += __shfl_xor_sync(0xffffffffu, dot0, o);
            dot1 += __shfl_xor_sync(0xffffffffu, dot1, o);
        }

        if (lane == 0) {
            float lam0 = hawkes(dot0, td0, b, psi, alpha, wt);
            float lam1 = hawkes(dot1, td1, b, psi, alpha, wt);
            if (surv0) acc_s += (double)lam0 * (double)tdu0;
            else       acc_l -= (double)logf(lam0 + 1e-7f);
            if (surv1) acc_s += (double)lam1 * (double)tdu1;
            else       acc_l -= (double)logf(lam1 + 1e-7f);
        }
    }

    // Warp-reduce acc_a (per-thread), fixed butterfly order -> deterministic.
#pragma unroll
    for (int o = 16; o; o >>= 1)
        acc_a += __shfl_xor_sync(0xffffffffu, acc_a, o);

    __shared__ double ssv[8], slm[8], sac[8];
    __shared__ bool   s_last;
    if (lane == 0) { ssv[warp] = acc_s; slm[warp] = acc_l; sac[warp] = acc_a; }
    __syncthreads();
    if (tid == 0) {
        double a = 0.0, c = 0.0, q = 0.0;
#pragma unroll
        for (int k = 0; k < 8; k++) { a += ssv[k]; c += slm[k]; q += sac[k]; }
        g_part_surv[blockIdx.x] = a;
        g_part_lam[blockIdx.x]  = c;
        g_part_acc[blockIdx.x]  = q;
        __threadfence();
        unsigned int prev = atomicAdd(&g_done, 1u);
        s_last = (prev == MAIN_BLOCKS - 1);
    }
    __syncthreads();

    if (s_last) {
        __shared__ double sh[256];
        // surv
        double s = 0.0;
        for (int j = tid; j < MAIN_BLOCKS; j += 256) s += g_part_surv[j];
        sh[tid] = s; __syncthreads();
        for (int o = 128; o; o >>= 1) { if (tid < o) sh[tid] += sh[tid + o]; __syncthreads(); }
        double surv = sh[0]; __syncthreads();
        // lambda
        double l = 0.0;
        for (int j = tid; j < MAIN_BLOCKS; j += 256) l += g_part_lam[j];
        sh[tid] = l; __syncthreads();
        for (int o = 128; o; o >>= 1) { if (tid < o) sh[tid] += sh[tid + o]; __syncthreads(); }
        double lam = sh[0]; __syncthreads();
        // accu
        double q = 0.0;
        for (int j = tid; j < MAIN_BLOCKS; j += 256) q += g_part_acc[j];
        sh[tid] = q; __syncthreads();
        for (int o = 128; o; o >>= 1) { if (tid < o) sh[tid] += sh[tid + o]; __syncthreads(); }

        if (tid == 0) {
            out[0] = (float)(lam / (double)NN);
            out[1] = (float)((surv / (double)SS + sh[0]) / (double)NN);
            g_done = 0;   // reset for next graph replay
        }
    }
}

// ---------------------------------------------------------------------------
// Inputs (metadata order):
//  0 all_embeddings (20000,256) f32   1 assoc (20000,) i32
//  2 src (8192,) i32                  3 pos_dst (8192,) i32
//  4 last_update (20000,) f32         5 cur_time (8192,) f32
//  6 u_non_embeddings (131072,256)    7 v_non_embeddings (131072,256)
//  8 last_time_pos (8192,) f32        9 td_surv_step (16,8192) f32
// 10 event_inten_accu (10000,10000)  11 W_omega (1,512)
// 12 b_omega (1,)  13 psi (1,)  14 alpha (1,)  15 w_t (1,)
// ---------------------------------------------------------------------------
extern "C" void kernel_launch(void* const* d_in, const int* in_sizes, int n_in,
                              void* d_out, int out_size)
{
    const float* emb     = (const float*)d_in[0];
    const int*   assoc   = (const int*)  d_in[1];
    const int*   src     = (const int*)  d_in[2];
    const int*   dst     = (const int*)  d_in[3];
    const float* lupd    = (const float*)d_in[4];
    const float* ctime   = (const float*)d_in[5];
    const float* u_non   = (const float*)d_in[6];
    const float* v_non   = (const float*)d_in[7];
    const float* ltp     = (const float*)d_in[8];
    const float* tdstep  = (const float*)d_in[9];
    const float* accu    = (const float*)d_in[10];
    const float* W       = (const float*)d_in[11];
    const float* b       = (const float*)d_in[12];
    const float* psi     = (const float*)d_in[13];
    const float* alpha   = (const float*)d_in[14];
    const float* w_t     = (const float*)d_in[15];
    float* out = (float*)d_out;

    pre_kernel<<<PRE_BLOCKS, 128>>>(assoc, src, dst, lupd, ctime, ltp);
    main_kernel<<<MAIN_BLOCKS, 256>>>(u_non, v_non, tdstep, emb, accu, W,
                                      b, psi, alpha, w_t, out);
}

// round 12
// speedup vs baseline: 1.5908x; 1.1414x over previous
#include <cuda_runtime.h>

// Problem constants
#define NN      8192        // N edges
#define EE      256         // embedding dim
#define SS      16          // survival steps
#define NSRC    10000
#define MINDST  10000
#define SURV_ROWS  (SS * NN)            // 131072
#define TOTAL_ROWS (SURV_ROWS + NN)     // 139264 (surv rows + edge rows)

#define PRE_BLOCKS  64                  // 64 x 128 = 8192 edges
#define MAIN_BLOCKS 296                 // 2 blocks/SM x 148 SMs, single wave
#define MAIN_WARPS  (MAIN_BLOCKS * 8)   // 2368 warps; 2 rows (1 pair) per iter
#define ROW_STRIDE  (2 * MAIN_WARPS)    // 4736

// Scratch (no allocation allowed -> __device__ globals)
__device__ float  g_td_uv[NN];
__device__ int    g_as[NN];
__device__ int    g_ad[NN];
__device__ float  g_ua[NN];
__device__ int    g_accu_idx[NN];
__device__ double g_part_surv[MAIN_BLOCKS];
__device__ double g_part_lam[MAIN_BLOCKS];
__device__ double g_part_acc[MAIN_BLOCKS];
__device__ unsigned int g_done = 0;

__device__ __forceinline__ float hawkes(float dot, float td,
                                        float b, float psi, float alpha, float w_t)
{
    float g  = dot + b + alpha * expf(-w_t * td * (1.0f / 5000.0f));
    float gp = fminf(fmaxf(g / (psi + 1e-7f), -75.0f), 75.0f);
    return psi * (log1pf(expf(-gp)) + gp);
}

// ---------------------------------------------------------------------------
// Kernel 1 (tiny): resolves indirection chains only.
// ---------------------------------------------------------------------------
__global__ __launch_bounds__(128)
void pre_kernel(const int*   __restrict__ assoc,
                const int*   __restrict__ src,
                const int*   __restrict__ dst,
                const float* __restrict__ last_update,
                const float* __restrict__ cur_time,
                const float* __restrict__ last_time_pos)
{
    int e = blockIdx.x * 128 + threadIdx.x;      // always < NN
    int   s   = src[e];
    int   d   = dst[e];
    int   as  = assoc[s];
    int   ad  = assoc[d];
    float lu  = fmaxf(last_update[as], last_update[ad]);
    float ltp = last_time_pos[e];

    g_td_uv[e]    = cur_time[e] - fmaxf(lu, ltp);
    g_as[e]       = as;
    g_ad[e]       = ad;
    g_ua[e]       = (ltp >= lu) ? 1.0f : 0.0f;
    g_accu_idx[e] = s * NSRC + (d - MINDST);
}

// ---------------------------------------------------------------------------
// Kernel 2: unified persistent streaming kernel.
//  - half-warp-per-row: lanes 0-15 own row r, lanes 16-31 own row r+1
//    (4-deep shfl reduction; the two hawkes tails run concurrently)
//  - double-buffered prefetch: next pair's 8 LDG.128 issued before the
//    current pair's reduce/tail -> memory pipe never idles per warp
//  - rows [0, SURV_ROWS): survival rows; [SURV_ROWS, TOTAL): edge rows
//  - threads gtid < NN also hide one random accu gather
//  - last-done block does the deterministic final reduction -> out
// ---------------------------------------------------------------------------
__global__ __launch_bounds__(256)
void main_kernel(const float* __restrict__ u,
                 const float* __restrict__ v,
                 const float* __restrict__ tdstep,
                 const float* __restrict__ emb,
                 const float* __restrict__ accu,
                 const float* __restrict__ W,
                 const float* __restrict__ b_,
                 const float* __restrict__ psi_,
                 const float* __restrict__ alpha_,
                 const float* __restrict__ wt_,
                 float* __restrict__ out)
{
    const int tid = threadIdx.x, warp = tid >> 5, lane = tid & 31;
    const int h = lane >> 4;          // which row of the pair this half owns
    const int p = lane & 15;          // position within the half-warp

    // W in registers: half-position p owns float4s {p, p+16, p+32, p+48}
    // of Wu (W[0..255]) and Wv (W[256..511]).  8 float4 = 32 regs.
    const float4* w4 = (const float4*)W;
    float4 wu[4], wv[4];
#pragma unroll
    for (int k = 0; k < 4; k++) {
        wu[k] = w4[p + 16 * k];
        wv[k] = w4[64 + p + 16 * k];
    }

    const float b     = b_[0];
    const float psi   = psi_[0];
    const float alpha = alpha_[0];
    const float wt    = wt_[0];

    double acc_s = 0.0;   // sum lambda_surv * td_uv      (held on p==0 lanes)
    double acc_l = 0.0;   // sum -log(lambda_uv + 1e-7)   (held on p==0 lanes)
    double acc_a = 0.0;   // sum use_accu * accu[...]     (all lanes)

    // Hidden random gather: one accu element per early global thread.
    int gtid = blockIdx.x * 256 + tid;
    if (gtid < NN)
        acc_a = (double)(g_ua[gtid] * __ldg(&accu[g_accu_idx[gtid]]));

    const float4* u4 = (const float4*)u;
    const float4* v4 = (const float4*)v;
    const float4* e4 = (const float4*)emb;

    float4 A[8], B[8];
    float tduA = 0.f, tdA = 0.f, tduB = 0.f, tdB = 0.f;
    bool  svA = false, svB = false;

    // --- helpers (macros so buffers stay in registers) -------------------
#define SETUP_LOAD(BUF, TDU, TD, SV, RP)                                     \
    do {                                                                     \
        int _rp = (RP);                                                      \
        const float4 *_pu, *_pv;                                             \
        (SV) = (_rp < SURV_ROWS);                                            \
        if (SV) {                                                            \
            _pu = u4 + (size_t)_rp * 64;                                     \
            _pv = v4 + (size_t)_rp * 64;                                     \
            (TDU) = g_td_uv[_rp & (NN - 1)];                                 \
            (TD)  = tdstep[_rp] * (TDU);                                     \
        } else {                                                             \
            int _e = _rp - SURV_ROWS;                                        \
            _pu = e4 + (size_t)g_as[_e] * 64;                                \
            _pv = e4 + (size_t)g_ad[_e] * 64;                                \
            (TDU) = 0.f;                                                     \
            (TD)  = g_td_uv[_e];                                             \
        }                                                                    \
        _Pragma("unroll")                                                    \
        for (int _k = 0; _k < 4; _k++) {                                     \
            (BUF)[_k]     = __ldcs(_pu + p + 16 * _k);                       \
            (BUF)[4 + _k] = __ldcs(_pv + p + 16 * _k);                       \
        }                                                                    \
    } while (0)

#define CONSUME(BUF, TDU, TD, SV)                                            \
    do {                                                                     \
        float _dot = 0.f;                                                    \
        _Pragma("unroll")                                                    \
        for (int _k = 0; _k < 4; _k++) {                                     \
            _dot += (BUF)[_k].x * wu[_k].x + (BUF)[_k].y * wu[_k].y          \
                  + (BUF)[_k].z * wu[_k].z + (BUF)[_k].w * wu[_k].w;         \
            _dot += (BUF)[4+_k].x * wv[_k].x + (BUF)[4+_k].y * wv[_k].y      \
                  + (BUF)[4+_k].z * wv[_k].z + (BUF)[4+_k].w * wv[_k].w;     \
        }                                                                    \
        _Pragma("unroll")                                                    \
        for (int _o = 8; _o; _o >>= 1)                                       \
            _dot += __shfl_xor_sync(0xffffffffu, _dot, _o);                  \
        float _lam = hawkes(_dot, (TD), b, psi, alpha, wt);                  \
        if (p == 0) {                                                        \
            if (SV) acc_s += (double)_lam * (double)(TDU);                   \
            else    acc_l -= (double)logf(_lam + 1e-7f);                     \
        }                                                                    \
    } while (0)
    // ---------------------------------------------------------------------

    int r = 2 * (blockIdx.x * 8 + warp);      // pair base, < ROW_STRIDE
    int rnext = r + ROW_STRIDE;

    SETUP_LOAD(A, tduA, tdA, svA, r + h);
    bool pendA = true, pendB = false;

    while (pendA || pendB) {
        if (pendA) {
            if (rnext < TOTAL_ROWS) {                 // prefetch into B
                SETUP_LOAD(B, tduB, tdB, svB, rnext + h);
                pendB = true;
                rnext += ROW_STRIDE;
            }
            CONSUME(A, tduA, tdA, svA);
            pendA = false;
        } else {
            if (rnext < TOTAL_ROWS) {                 // prefetch into A
                SETUP_LOAD(A, tduA, tdA, svA, rnext + h);
                pendA = true;
                rnext += ROW_STRIDE;
            }
            CONSUME(B, tduB, tdB, svB);
            pendB = false;
        }
    }

    // Warp reduce (fixed butterfly order -> deterministic).
#pragma unroll
    for (int o = 16; o; o >>= 1) {
        acc_s += __shfl_xor_sync(0xffffffffu, acc_s, o);
        acc_l += __shfl_xor_sync(0xffffffffu, acc_l, o);
        acc_a += __shfl_xor_sync(0xffffffffu, acc_a, o);
    }

    __shared__ double ssv[8], slm[8], sac[8];
    __shared__ bool   s_last;
    if (lane == 0) { ssv[warp] = acc_s; slm[warp] = acc_l; sac[warp] = acc_a; }
    __syncthreads();
    if (tid == 0) {
        double a = 0.0, c = 0.0, q = 0.0;
#pragma unroll
        for (int k = 0; k < 8; k++) { a += ssv[k]; c += slm[k]; q += sac[k]; }
        g_part_surv[blockIdx.x] = a;
        g_part_lam[blockIdx.x]  = c;
        g_part_acc[blockIdx.x]  = q;
        __threadfence();
        unsigned int prev = atomicAdd(&g_done, 1u);
        s_last = (prev == MAIN_BLOCKS - 1);
    }
    __syncthreads();

    if (s_last) {
        __shared__ double sh[256];
        double s = 0.0;
        for (int j = tid; j < MAIN_BLOCKS; j += 256) s += g_part_surv[j];
        sh[tid] = s; __syncthreads();
        for (int o = 128; o; o >>= 1) { if (tid < o) sh[tid] += sh[tid + o]; __syncthreads(); }
        double surv = sh[0]; __syncthreads();

        double l = 0.0;
        for (int j = tid; j < MAIN_BLOCKS; j += 256) l += g_part_lam[j];
        sh[tid] = l; __syncthreads();
        for (int o = 128; o; o >>= 1) { if (tid < o) sh[tid] += sh[tid + o]; __syncthreads(); }
        double lam = sh[0]; __syncthreads();

        double q = 0.0;
        for (int j = tid; j < MAIN_BLOCKS; j += 256) q += g_part_acc[j];
        sh[tid] = q; __syncthreads();
        for (int o = 128; o; o >>= 1) { if (tid < o) sh[tid] += sh[tid + o]; __syncthreads(); }

        if (tid == 0) {
            out[0] = (float)(lam / (double)NN);
            out[1] = (float)((surv / (double)SS + sh[0]) / (double)NN);
            g_done = 0;   // reset for next graph replay
        }
    }
#undef SETUP_LOAD
#undef CONSUME
}

// ---------------------------------------------------------------------------
// Inputs (metadata order):
//  0 all_embeddings (20000,256) f32   1 assoc (20000,) i32
//  2 src (8192,) i32                  3 pos_dst (8192,) i32
//  4 last_update (20000,) f32         5 cur_time (8192,) f32
//  6 u_non_embeddings (131072,256)    7 v_non_embeddings (131072,256)
//  8 last_time_pos (8192,) f32        9 td_surv_step (16,8192) f32
// 10 event_inten_accu (10000,10000)  11 W_omega (1,512)
// 12 b_omega (1,)  13 psi (1,)  14 alpha (1,)  15 w_t (1,)
// ---------------------------------------------------------------------------
extern "C" void kernel_launch(void* const* d_in, const int* in_sizes, int n_in,
                              void* d_out, int out_size)
{
    const float* emb     = (const float*)d_in[0];
    const int*   assoc   = (const int*)  d_in[1];
    const int*   src     = (const int*)  d_in[2];
    const int*   dst     = (const int*)  d_in[3];
    const float* lupd    = (const float*)d_in[4];
    const float* ctime   = (const float*)d_in[5];
    const float* u_non   = (const float*)d_in[6];
    const float* v_non   = (const float*)d_in[7];
    const float* ltp     = (const float*)d_in[8];
    const float* tdstep  = (const float*)d_in[9];
    const float* accu    = (const float*)d_in[10];
    const float* W       = (const float*)d_in[11];
    const float* b       = (const float*)d_in[12];
    const float* psi     = (const float*)d_in[13];
    const float* alpha   = (const float*)d_in[14];
    const float* w_t     = (const float*)d_in[15];
    float* out = (float*)d_out;

    pre_kernel<<<PRE_BLOCKS, 128>>>(assoc, src, dst, lupd, ctime, ltp);
    main_kernel<<<MAIN_BLOCKS, 256>>>(u_non, v_non, tdstep, emb, accu, W,
                                      b, psi, alpha, w_t, out);
}